// round 3
// baseline (speedup 1.0000x reference)
#include <cuda_runtime.h>
#include <cuda_bf16.h>

// ---- model constants ----
#define BB 2
#define SS 2048
#define DD 1024
#define NLAY 8
#define NV1 200
#define NV2 160
#define NCH 128       // scan chunks over S
#define TC 16         // timesteps per chunk (NCH*TC == SS)
#define NROWS (BB*SS) // 4096
#define EPSF 1e-6f

typedef unsigned long long ull;

// ---- device scratch (no allocations allowed) ----
__device__ float g_X[NROWS * DD];        // activations [B,S,D]  (16.8 MB, L2-resident)
__device__ float g_R[NROWS];             // per-row rmsnorm factors
__device__ float g_HLOC[BB * NCH * DD];  // per-chunk local scan terminal state
__device__ float g_HIN[BB * NCH * DD];   // per-chunk incoming state

// ---- f32x2 packed-math helpers (2x fp32 FMA rate on sm_103a) ----
__device__ __forceinline__ ull pack2(float lo, float hi) {
    ull r; asm("mov.b64 %0, {%1, %2};" : "=l"(r) : "f"(lo), "f"(hi)); return r;
}
__device__ __forceinline__ void unpack2(ull v, float& lo, float& hi) {
    asm("mov.b64 {%0, %1}, %2;" : "=f"(lo), "=f"(hi) : "l"(v));
}
__device__ __forceinline__ ull ffma2(ull a, ull b, ull c) {
    ull d; asm("fma.rn.f32x2 %0, %1, %2, %3;" : "=l"(d) : "l"(a), "l"(b), "l"(c)); return d;
}

__device__ __forceinline__ float sigmoidf_acc(float x) { return 1.f / (1.f + expf(-x)); }

// jax.nn.gelu default = tanh approximation
__device__ __forceinline__ float geluf(float x) {
    float x3 = x * x * x;
    return 0.5f * x * (1.f + tanhf(0.7978845608028654f * (x + 0.044715f * x3)));
}

// block reduce (256 threads) with broadcast; sred must have >= 33 floats
__device__ __forceinline__ float blockReduceBcast(float v, float* sred) {
    int lane = threadIdx.x & 31, w = threadIdx.x >> 5;
    #pragma unroll
    for (int o = 16; o > 0; o >>= 1) v += __shfl_down_sync(0xffffffffu, v, o);
    if (lane == 0) sred[w] = v;
    __syncthreads();
    if (w == 0) {
        float t = (lane < 8) ? sred[lane] : 0.f;
        #pragma unroll
        for (int o = 4; o > 0; o >>= 1) t += __shfl_down_sync(0xffffffffu, t, o);
        if (lane == 0) sred[32] = t;
    }
    __syncthreads();
    return sred[32];
}

// ============================================================
// 1) TT-rank-1 embedding: x[row, d1*32+d2] = c1[id/160, d1]*c2[id%160, d2]
// ============================================================
__global__ void k_embed(const int* __restrict__ ids,
                        const float* __restrict__ c1,
                        const float* __restrict__ c2) {
    __shared__ float s1[32], s2[32];
    int row = blockIdx.x, tid = threadIdx.x;
    int id = ids[row];
    if (tid < 32) s1[tid] = c1[(id / NV2) * 32 + tid];
    else if (tid < 64) s2[tid - 32] = c2[(id % NV2) * 32 + (tid - 32)];
    __syncthreads();
    float* xr = g_X + (size_t)row * DD;
    #pragma unroll
    for (int q = 0; q < 4; q++) {
        int d = tid + q * 256;
        xr[d] = s1[d >> 5] * s2[d & 31];
    }
}

// ============================================================
// 2) per-row rmsnorm factor r = rsqrt(mean(x^2)+eps)
// ============================================================
__global__ void k_rms() {
    __shared__ float sred[33];
    int row = blockIdx.x, tid = threadIdx.x;
    const float* xr = g_X + (size_t)row * DD;
    float s = 0.f;
    #pragma unroll
    for (int q = 0; q < 4; q++) { float v = xr[tid + q * 256]; s += v * v; }
    float tot = blockReduceBcast(s, sred);
    if (tid == 0) g_R[row] = rsqrtf(tot * (1.f / (float)DD) + EPSF);
}

// ============================================================
// 3) scan pass A: per-chunk local scan (h0 = 0), record terminal h
//    grid: B*NCH blocks, 256 threads, 4 channels/thread
// ============================================================
__global__ void k_scan_partial(const float* __restrict__ lam,
                               const float* __restrict__ vv,
                               const float* __restrict__ n1w) {
    int blk = blockIdx.x; int b = blk >> 7; int ch = blk & (NCH - 1);
    int tid = threadIdx.x;
    float a[4], vi[4], w[4], h[4];
    #pragma unroll
    for (int q = 0; q < 4; q++) {
        int c = tid + q * 256;
        a[q] = sigmoidf_acc(lam[c]); vi[q] = vv[c]; w[q] = n1w[c]; h[q] = 0.f;
    }
    int row0 = b * SS + ch * TC;
    for (int t = 0; t < TC; t++) {
        const float* xr = g_X + (size_t)(row0 + t) * DD;
        float r = g_R[row0 + t];
        #pragma unroll
        for (int q = 0; q < 4; q++) {
            int c = tid + q * 256;
            float xn = xr[c] * r * w[q];
            h[q] = a[q] * h[q] + vi[q] * xn;
        }
    }
    #pragma unroll
    for (int q = 0; q < 4; q++)
        g_HLOC[(size_t)(b * NCH + ch) * DD + tid + q * 256] = h[q];
}

// ============================================================
// 4) scan pass B: combine chunk prefixes (serial over 128 chunks / channel)
//    2048 threads total
// ============================================================
__global__ void k_combine(const float* __restrict__ lam) {
    int g = blockIdx.x * 256 + threadIdx.x;   // 0..2047
    int b = g >> 10; int c = g & 1023;
    float a = sigmoidf_acc(lam[c]);
    float aT = a;
    #pragma unroll
    for (int i = 0; i < 4; i++) aT *= aT;     // a^16
    float h = 0.f;
    for (int k = 0; k < NCH; k++) {
        size_t idx = (size_t)(b * NCH + k) * DD + c;
        g_HIN[idx] = h;
        h = aT * h + g_HLOC[idx];
    }
}

// ============================================================
// 5) scan pass C: redo chunk scan with true h0, write x += u*h (in place)
// ============================================================
__global__ void k_scan_apply(const float* __restrict__ lam,
                             const float* __restrict__ vv,
                             const float* __restrict__ uu,
                             const float* __restrict__ n1w) {
    int blk = blockIdx.x; int b = blk >> 7; int ch = blk & (NCH - 1);
    int tid = threadIdx.x;
    float a[4], vi[4], uo[4], w[4], h[4];
    #pragma unroll
    for (int q = 0; q < 4; q++) {
        int c = tid + q * 256;
        a[q] = sigmoidf_acc(lam[c]); vi[q] = vv[c]; uo[q] = uu[c]; w[q] = n1w[c];
        h[q] = g_HIN[(size_t)(b * NCH + ch) * DD + c];
    }
    int row0 = b * SS + ch * TC;
    for (int t = 0; t < TC; t++) {
        float* xr = g_X + (size_t)(row0 + t) * DD;
        float r = g_R[row0 + t];
        #pragma unroll
        for (int q = 0; q < 4; q++) {
            int c = tid + q * 256;
            float xv = xr[c];
            float xn = xv * r * w[q];
            h[q] = a[q] * h[q] + vi[q] * xn;
            xr[c] = xv + uo[q] * h[q];
        }
    }
}

// ============================================================
// 6) rank-2 FFN with fused rmsnorm: one block per row
//    x += gelu(rmsnorm(x)*n2w @ w1) @ w2
// ============================================================
__global__ void k_ffn(const float* __restrict__ n2w,
                      const float* __restrict__ w1,   // [D][2]
                      const float* __restrict__ w2) { // [2][D]
    __shared__ float sred[32];
    int row = blockIdx.x, tid = threadIdx.x;
    int lane = tid & 31, wrp = tid >> 5;
    float* xr = g_X + (size_t)row * DD;
    float xv[4]; float s0 = 0.f, s1 = 0.f, s2 = 0.f;
    #pragma unroll
    for (int q = 0; q < 4; q++) {
        int c = tid + q * 256;
        float v = xr[c]; xv[q] = v;
        float xw = v * n2w[c];
        s0 += v * v;
        s1 += xw * w1[c * 2 + 0];
        s2 += xw * w1[c * 2 + 1];
    }
    #pragma unroll
    for (int o = 16; o > 0; o >>= 1) {
        s0 += __shfl_down_sync(0xffffffffu, s0, o);
        s1 += __shfl_down_sync(0xffffffffu, s1, o);
        s2 += __shfl_down_sync(0xffffffffu, s2, o);
    }
    if (lane == 0) { sred[wrp] = s0; sred[8 + wrp] = s1; sred[16 + wrp] = s2; }
    __syncthreads();
    if (tid < 32) {
        float b0 = (lane < 8) ? sred[lane] : 0.f;
        float b1 = (lane < 8) ? sred[8 + lane] : 0.f;
        float b2 = (lane < 8) ? sred[16 + lane] : 0.f;
        #pragma unroll
        for (int o = 4; o > 0; o >>= 1) {
            b0 += __shfl_down_sync(0xffffffffu, b0, o);
            b1 += __shfl_down_sync(0xffffffffu, b1, o);
            b2 += __shfl_down_sync(0xffffffffu, b2, o);
        }
        if (lane == 0) { sred[24] = b0; sred[25] = b1; sred[26] = b2; }
    }
    __syncthreads();
    float r = rsqrtf(sred[24] * (1.f / (float)DD) + EPSF);
    float g0 = geluf(r * sred[25]);
    float g1 = geluf(r * sred[26]);
    #pragma unroll
    for (int q = 0; q < 4; q++) {
        int c = tid + q * 256;
        xr[c] = xv[q] + g0 * w2[c] + g1 * w2[DD + c];
    }
}

// ============================================================
// 7) final rmsnorm + TT-factored output projection
//    per row: T[d1,v2] = sum_d2 xf[d1,d2]*c2[v2,d2]  (f32x2, d2-pairs)
//             out[v1,v2] = sum_d1 c1[v1,d1]*T[d1,v2] (f32x2, v1-pairs)
// smem layout (floats):
//   sXF  [32][34]   @ 0       (xf, row pitch 34 for 64-bit conflict avoidance)
//   sC2  [160][32]  @ 1088
//   sC1p [100][32]x2@ 6208    (v1-pair packed core1)
//   sT   [32][161]  @ 12608
// total 17760 floats = 71040 B
// ============================================================
#define PROJ_SMEM_FLOATS 17760
__global__ void __launch_bounds__(256) k_proj(const float* __restrict__ c1,
                                              const float* __restrict__ c2,
                                              const float* __restrict__ fnw,
                                              float* __restrict__ out) {
    extern __shared__ float sm[];
    float* sXF  = sm;            // [32][34]
    float* sC2  = sm + 1088;     // [160][32]
    float* sC1p = sm + 6208;     // pairs: ((v1>>1)*32 + k)*2 + (v1&1)
    float* sT   = sm + 12608;    // [32][161]
    __shared__ float sred[33];

    int row = blockIdx.x, tid = threadIdx.x;
    const float* xr = g_X + (size_t)row * DD;

    // stage weights into smem + accumulate x^2
    float xv[4]; float s0 = 0.f;
    #pragma unroll
    for (int q = 0; q < 4; q++) { float v = xr[tid + q * 256]; xv[q] = v; s0 += v * v; }
    for (int i = tid; i < NV2 * 32; i += 256) sC2[i] = c2[i];
    for (int i = tid; i < NV1 * 32; i += 256) {
        int v1 = i >> 5, k = i & 31;
        sC1p[((v1 >> 1) * 32 + k) * 2 + (v1 & 1)] = c1[i];
    }
    float tot = blockReduceBcast(s0, sred);
    float r = rsqrtf(tot * (1.f / (float)DD) + EPSF);
    #pragma unroll
    for (int q = 0; q < 4; q++) {
        int d = tid + q * 256; int d1 = d >> 5, d2 = d & 31;
        sXF[d1 * 34 + d2] = xv[q] * r * fnw[d];
    }
    __syncthreads();

    // ---- T stage: thread owns d1 = tid&31, v2 block of 20 ----
    {
        int d1 = tid & 31;
        int v2b = (tid >> 5) * 20;
        const ull* xfp = (const ull*)(sXF + d1 * 34);   // 16 x (d2 pair)
        ull xreg[16];
        #pragma unroll
        for (int kk = 0; kk < 16; kk++) xreg[kk] = xfp[kk];
        for (int n = 0; n < 20; n++) {
            int v2 = v2b + n;
            const ull* c2p = (const ull*)(sC2 + v2 * 32); // broadcast across warp
            ull acc = 0ull;
            #pragma unroll
            for (int kk = 0; kk < 16; kk++) acc = ffma2(xreg[kk], c2p[kk], acc);
            float lo, hi; unpack2(acc, lo, hi);
            sT[d1 * 161 + v2] = lo + hi;
        }
    }
    __syncthreads();

    // ---- stage 2: 800 tiles of (8 v1 x 5 v2); lane = v2 group (stride-5, cf) ----
    float* orow = out + (size_t)row * (NV1 * NV2);
    for (int it = 0; it < 4; it++) {
        int tile = it * 256 + tid;
        if (tile >= 800) break;
        int v2g = tile & 31, v1g = tile >> 5;
        int v2b = v2g * 5;
        const ull* c1p = ((const ull*)sC1p) + v1g * 4 * 32;
        ull acc[4][5];
        #pragma unroll
        for (int i = 0; i < 4; i++)
            #pragma unroll
            for (int j = 0; j < 5; j++) acc[i][j] = 0ull;
        #pragma unroll 8
        for (int k = 0; k < 32; k++) {
            ull cp[4];
            #pragma unroll
            for (int i = 0; i < 4; i++) cp[i] = c1p[i * 32 + k]; // broadcast
            ull td[5];
            #pragma unroll
            for (int j = 0; j < 5; j++) {
                float t = sT[k * 161 + v2b + j];                 // conflict-free
                td[j] = pack2(t, t);
            }
            #pragma unroll
            for (int i = 0; i < 4; i++)
                #pragma unroll
                for (int j = 0; j < 5; j++) acc[i][j] = ffma2(cp[i], td[j], acc[i][j]);
        }
        #pragma unroll
        for (int i = 0; i < 4; i++) {
            int v1 = v1g * 8 + 2 * i;
            float* p0 = orow + v1 * NV2 + v2b;
            float* p1 = p0 + NV2;
            #pragma unroll
            for (int j = 0; j < 5; j++) {
                float lo, hi; unpack2(acc[i][j], lo, hi);
                p0[j] = lo; p1[j] = hi;
            }
        }
    }
}

// ============================================================
// launcher
// ============================================================
extern "C" void kernel_launch(void* const* d_in, const int* in_sizes, int n_in,
                              void* d_out, int out_size) {
    const int*   ids   = (const int*)d_in[0];
    const float* core1 = (const float*)d_in[1];
    const float* core2 = (const float*)d_in[2];
    const float* lam   = (const float*)d_in[3];
    const float* uu    = (const float*)d_in[4];
    const float* vv    = (const float*)d_in[5];
    const float* w1    = (const float*)d_in[6];
    const float* w2    = (const float*)d_in[7];
    const float* n1w   = (const float*)d_in[8];
    const float* n2w   = (const float*)d_in[9];
    const float* fnw   = (const float*)d_in[10];
    float* out = (float*)d_out;

    cudaFuncSetAttribute(k_proj, cudaFuncAttributeMaxDynamicSharedMemorySize,
                         PROJ_SMEM_FLOATS * 4);

    k_embed<<<NROWS, 256>>>(ids, core1, core2);
    for (int l = 0; l < NLAY; l++) {
        const float* laml = lam + l * DD;
        k_rms<<<NROWS, 256>>>();
        k_scan_partial<<<BB * NCH, 256>>>(laml, vv + l * DD, n1w + l * DD);
        k_combine<<<8, 256>>>(laml);
        k_scan_apply<<<BB * NCH, 256>>>(laml, vv + l * DD, uu + l * DD, n1w + l * DD);
        k_ffn<<<NROWS, 256>>>(n2w + l * DD, w1 + l * DD * 2, w2 + l * 2 * DD);
    }
    k_proj<<<NROWS, 256, PROJ_SMEM_FLOATS * 4>>>(core1, core2, fnw, out);
}

// round 5
// speedup vs baseline: 2.0079x; 2.0079x over previous
#include <cuda_runtime.h>
#include <cuda_bf16.h>

// ---- model constants ----
#define BB 2
#define SS 2048
#define DD 1024
#define NLAY 8
#define NV1 200
#define NV2 160
#define NCH 128       // scan chunks over S
#define TC 16         // timesteps per chunk (NCH*TC == SS)
#define NROWS (BB*SS) // 4096
#define EPSF 1e-6f

typedef unsigned long long ull;

// ---- device scratch (no allocations allowed) ----
__device__ float g_X[NROWS * DD];        // activations [B,S,D]  (16.8 MB, L2-resident)
__device__ float g_R[NROWS];             // per-row rmsnorm factors (for current layer)
__device__ float g_HLOC[BB * NCH * DD];  // per-chunk local scan terminal state
__device__ float g_HIN[BB * NCH * DD];   // per-chunk incoming state

// ---- f32x2 packed-math helpers (2x fp32 FMA rate on sm_103a) ----
__device__ __forceinline__ ull pack2(float lo, float hi) {
    ull r; asm("mov.b64 %0, {%1, %2};" : "=l"(r) : "f"(lo), "f"(hi)); return r;
}
__device__ __forceinline__ void unpack2(ull v, float& lo, float& hi) {
    asm("mov.b64 {%0, %1}, %2;" : "=f"(lo), "=f"(hi) : "l"(v));
}
__device__ __forceinline__ ull ffma2(ull a, ull b, ull c) {
    ull d; asm("fma.rn.f32x2 %0, %1, %2, %3;" : "=l"(d) : "l"(a), "l"(b), "l"(c)); return d;
}

__device__ __forceinline__ float sigmoidf_acc(float x) { return 1.f / (1.f + expf(-x)); }

// jax.nn.gelu default = tanh approximation
__device__ __forceinline__ float geluf(float x) {
    float x3 = x * x * x;
    return 0.5f * x * (1.f + tanhf(0.7978845608028654f * (x + 0.044715f * x3)));
}

// ---- block reduce helpers (256 threads) ----
// 1-wide reduce with broadcast; sbuf >= 48 floats
__device__ __forceinline__ float blockReduce1(float v, float* sbuf) {
    int lane = threadIdx.x & 31, w = threadIdx.x >> 5;
    #pragma unroll
    for (int o = 16; o > 0; o >>= 1) v += __shfl_down_sync(0xffffffffu, v, o);
    if (lane == 0) sbuf[w] = v;
    __syncthreads();
    if (w == 0) {
        float t = (lane < 8) ? sbuf[lane] : 0.f;
        #pragma unroll
        for (int o = 4; o > 0; o >>= 1) t += __shfl_down_sync(0xffffffffu, t, o);
        if (lane == 0) sbuf[40] = t;
    }
    __syncthreads();
    return sbuf[40];
}

// 5-wide simultaneous reduce with broadcast; sbuf >= 48 floats.
// Safe for back-to-back calls: slots [0..39] (per-warp) are rewritten only
// after the first __syncthreads of the next call orders them w.r.t. the
// broadcast reads of [40..44].
__device__ __forceinline__ void blockReduce5(float* p, float* sbuf) {
    int lane = threadIdx.x & 31, w = threadIdx.x >> 5;
    #pragma unroll
    for (int o = 16; o > 0; o >>= 1) {
        #pragma unroll
        for (int j = 0; j < 5; j++) p[j] += __shfl_down_sync(0xffffffffu, p[j], o);
    }
    if (lane == 0) {
        #pragma unroll
        for (int j = 0; j < 5; j++) sbuf[w * 5 + j] = p[j];
    }
    __syncthreads();
    if (w == 0) {
        float q[5];
        #pragma unroll
        for (int j = 0; j < 5; j++) q[j] = (lane < 8) ? sbuf[lane * 5 + j] : 0.f;
        #pragma unroll
        for (int o = 4; o > 0; o >>= 1) {
            #pragma unroll
            for (int j = 0; j < 5; j++) q[j] += __shfl_down_sync(0xffffffffu, q[j], o);
        }
        if (lane == 0) {
            #pragma unroll
            for (int j = 0; j < 5; j++) sbuf[40 + j] = q[j];
        }
    }
    __syncthreads();
    #pragma unroll
    for (int j = 0; j < 5; j++) p[j] = sbuf[40 + j];
}

// ============================================================
// 1) fused embed: TT-rank-1 embedding + rmsnorm factor + layer-0 partial scan
//    grid: B*NCH blocks of 256 threads; block = one chunk of TC rows
// ============================================================
__global__ void __launch_bounds__(256) k_embed_fused(
        const int* __restrict__ ids,
        const float* __restrict__ c1,
        const float* __restrict__ c2,
        const float* __restrict__ lam0,
        const float* __restrict__ vv0,
        const float* __restrict__ n1w0) {
    __shared__ float sbuf[48];
    __shared__ float s1[2][32], s2[2][32];
    int blk = blockIdx.x; int b = blk >> 7; int ch = blk & (NCH - 1);
    int tid = threadIdx.x;

    float a[4], vi[4], N1[4], h[4];
    #pragma unroll
    for (int q = 0; q < 4; q++) {
        int c = tid + q * 256;
        a[q] = sigmoidf_acc(lam0[c]); vi[q] = vv0[c]; N1[q] = n1w0[c]; h[q] = 0.f;
    }
    int row0 = b * SS + ch * TC;
    for (int t = 0; t < TC; t++) {
        int row = row0 + t;
        int buf = t & 1;
        if (tid < 64) {
            int id = ids[row];               // uniform load (broadcast)
            if (tid < 32) s1[buf][tid] = c1[(id / NV2) * 32 + tid];
            else          s2[buf][tid - 32] = c2[(id % NV2) * 32 + (tid - 32)];
        }
        __syncthreads();
        float x[4]; float s0 = 0.f;
        #pragma unroll
        for (int q = 0; q < 4; q++) {
            int d = tid + q * 256;
            x[q] = s1[buf][d >> 5] * s2[buf][d & 31];
            s0 += x[q] * x[q];
        }
        float tot = blockReduce1(s0, sbuf);
        float r = rsqrtf(tot * (1.f / (float)DD) + EPSF);
        float* xr = g_X + (size_t)row * DD;
        #pragma unroll
        for (int q = 0; q < 4; q++) {
            int c = tid + q * 256;
            xr[c] = x[q];
            float z = x[q] * r * N1[q];
            h[q] = a[q] * h[q] + vi[q] * z;
        }
        if (tid == 0) g_R[row] = r;
    }
    size_t hidx = (size_t)(b * NCH + ch) * DD;
    #pragma unroll
    for (int q = 0; q < 4; q++) g_HLOC[hidx + tid + q * 256] = h[q];
}

// ============================================================
// 2) scan combine: chunk prefixes, batched-prefetch serial (MLP=16)
//    h_in[k] = sum_{j<k} aT^{k-1-j} hloc[j],  aT = a^TC
// ============================================================
__global__ void k_combine(const float* __restrict__ lam) {
    int g = blockIdx.x * 256 + threadIdx.x;   // 0..2047
    int b = g >> 10; int c = g & 1023;
    float a = sigmoidf_acc(lam[c]);
    float aT = a;
    #pragma unroll
    for (int i = 0; i < 4; i++) aT *= aT;     // a^16
    float h = 0.f;
    for (int kb = 0; kb < NCH; kb += 16) {
        float loc[16];
        #pragma unroll
        for (int i = 0; i < 16; i++)
            loc[i] = g_HLOC[(size_t)(b * NCH + kb + i) * DD + c];
        #pragma unroll
        for (int i = 0; i < 16; i++) {
            g_HIN[(size_t)(b * NCH + kb + i) * DD + c] = h;
            h = aT * h + loc[i];
        }
    }
}

// ============================================================
// 3) fused layer kernel: scan-apply(l) + FFN(l, rmsnorm fused) +
//    next-layer rms factor (algebraic) + next-layer partial scan
//    grid: B*NCH blocks of 256 threads; block = one chunk of TC rows
// ============================================================
__global__ void __launch_bounds__(256) k_fused(
        const float* __restrict__ lam, const float* __restrict__ vv,
        const float* __restrict__ uu,  const float* __restrict__ n1w,
        const float* __restrict__ n2w, const float* __restrict__ w1,
        const float* __restrict__ w2,
        const float* __restrict__ lam_n, const float* __restrict__ vv_n,
        const float* __restrict__ n1w_n, int last) {
    __shared__ float sbuf[48];
    int blk = blockIdx.x; int b = blk >> 7; int ch = blk & (NCH - 1);
    int tid = threadIdx.x;

    float a[4], vi[4], uo[4], N1[4], N2[4], W1a[4], W1b[4], W2a[4], W2b[4];
    float a2[4], vi2[4], N1n[4];
    float h[4], h2[4];
    size_t hidx = (size_t)(b * NCH + ch) * DD;

    #pragma unroll
    for (int q = 0; q < 4; q++) {
        int c = tid + q * 256;
        a[q]  = sigmoidf_acc(lam[c]); vi[q] = vv[c]; uo[q] = uu[c];
        N1[q] = n1w[c]; N2[q] = n2w[c];
        W1a[q] = w1[2 * c]; W1b[q] = w1[2 * c + 1];
        W2a[q] = w2[c];     W2b[q] = w2[DD + c];
        h[q] = g_HIN[hidx + c];
        h2[q] = 0.f;
        if (!last) {
            a2[q] = sigmoidf_acc(lam_n[c]); vi2[q] = vv_n[c]; N1n[q] = n1w_n[c];
        } else { a2[q] = 0.f; vi2[q] = 0.f; N1n[q] = 0.f; }
    }

    // per-layer quadratic sums of w2 rows (for algebraic second rmsnorm)
    float Qaa, Qbb, Qab;
    {
        float p[5] = {0.f, 0.f, 0.f, 0.f, 0.f};
        #pragma unroll
        for (int q = 0; q < 4; q++) {
            p[0] += W2a[q] * W2a[q];
            p[1] += W2b[q] * W2b[q];
            p[2] += W2a[q] * W2b[q];
        }
        blockReduce5(p, sbuf);
        Qaa = p[0]; Qbb = p[1]; Qab = p[2];
    }

    int row0 = b * SS + ch * TC;
    float x[4]; float r;
    {
        const float* xr = g_X + (size_t)row0 * DD;
        #pragma unroll
        for (int q = 0; q < 4; q++) x[q] = xr[tid + q * 256];
        r = g_R[row0];
    }

    for (int t = 0; t < TC; t++) {
        int row = row0 + t;
        // prefetch next row's x (pre-update value) + r to hide L2 latency
        float xnext[4]; float rnext_row = 0.f;
        if (t + 1 < TC) {
            const float* x2 = g_X + (size_t)(row + 1) * DD;
            #pragma unroll
            for (int q = 0; q < 4; q++) xnext[q] = x2[tid + q * 256];
            rnext_row = g_R[row + 1];
        }

        float xp[4];
        float p[5] = {0.f, 0.f, 0.f, 0.f, 0.f};
        #pragma unroll
        for (int q = 0; q < 4; q++) {
            float z = x[q] * r * N1[q];
            h[q] = a[q] * h[q] + vi[q] * z;
            xp[q] = x[q] + uo[q] * h[q];
            p[0] += xp[q] * xp[q];
            float xw = xp[q] * N2[q];
            p[1] += xw * W1a[q];
            p[2] += xw * W1b[q];
            p[3] += xp[q] * W2a[q];
            p[4] += xp[q] * W2b[q];
        }
        blockReduce5(p, sbuf);
        float r2 = rsqrtf(p[0] * (1.f / (float)DD) + EPSF);
        float g0 = geluf(r2 * p[1]);
        float g1 = geluf(r2 * p[2]);
        // ||x_final||^2 expanded algebraically (no second reduce)
        float sf = p[0] + 2.f * (g0 * p[3] + g1 * p[4])
                 + g0 * g0 * Qaa + g1 * g1 * Qbb + 2.f * g0 * g1 * Qab;
        float rnext = rsqrtf(sf * (1.f / (float)DD) + EPSF);

        float* xo = g_X + (size_t)row * DD;
        #pragma unroll
        for (int q = 0; q < 4; q++) {
            float xf = xp[q] + g0 * W2a[q] + g1 * W2b[q];
            xo[tid + q * 256] = xf;
            if (!last) {
                float z2 = xf * rnext * N1n[q];
                h2[q] = a2[q] * h2[q] + vi2[q] * z2;
            }
        }
        if (tid == 0) g_R[row] = rnext;   // rms factor for next layer (or final norm)

        if (t + 1 < TC) {
            #pragma unroll
            for (int q = 0; q < 4; q++) x[q] = xnext[q];
            r = rnext_row;
        }
    }
    if (!last) {
        #pragma unroll
        for (int q = 0; q < 4; q++) g_HLOC[hidx + tid + q * 256] = h2[q];
    }
}

// ============================================================
// 4) final TT-factored output projection (uses precomputed g_R)
//    per row: T[d1,v2] = sum_d2 xf[d1,d2]*c2[v2,d2]  (f32x2, d2-pairs)
//             out[v1,v2] = sum_d1 c1[v1,d1]*T[d1,v2] (f32x2, v1-pairs)
// smem layout (floats):
//   sXF  [32][34]   @ 0
//   sC2  [160][32]  @ 1088
//   sC1p [100][32]x2@ 6208    (v1-pair packed core1)
//   sT   [32][161]  @ 12608
// total 17760 floats = 71040 B
// ============================================================
#define PROJ_SMEM_FLOATS 17760
__global__ void __launch_bounds__(256) k_proj(const float* __restrict__ c1,
                                              const float* __restrict__ c2,
                                              const float* __restrict__ fnw,
                                              float* __restrict__ out) {
    extern __shared__ float sm[];
    float* sXF  = sm;            // [32][34]
    float* sC2  = sm + 1088;     // [160][32]
    float* sC1p = sm + 6208;     // pairs: ((v1>>1)*32 + k)*2 + (v1&1)
    float* sT   = sm + 12608;    // [32][161]

    int row = blockIdx.x, tid = threadIdx.x;
    const float* xr = g_X + (size_t)row * DD;
    float r = g_R[row];          // final-norm factor computed by layer-7 fused kernel

    #pragma unroll
    for (int q = 0; q < 4; q++) {
        int d = tid + q * 256; int d1 = d >> 5, d2 = d & 31;
        sXF[d1 * 34 + d2] = xr[d] * r * fnw[d];
    }
    for (int i = tid; i < NV2 * 32; i += 256) sC2[i] = c2[i];
    for (int i = tid; i < NV1 * 32; i += 256) {
        int v1 = i >> 5, k = i & 31;
        sC1p[((v1 >> 1) * 32 + k) * 2 + (v1 & 1)] = c1[i];
    }
    __syncthreads();

    // ---- T stage: thread owns d1 = tid&31, v2 block of 20 ----
    {
        int d1 = tid & 31;
        int v2b = (tid >> 5) * 20;
        const ull* xfp = (const ull*)(sXF + d1 * 34);   // 16 x (d2 pair)
        ull xreg[16];
        #pragma unroll
        for (int kk = 0; kk < 16; kk++) xreg[kk] = xfp[kk];
        for (int n = 0; n < 20; n++) {
            int v2 = v2b + n;
            const ull* c2p = (const ull*)(sC2 + v2 * 32); // broadcast across warp
            ull acc = 0ull;
            #pragma unroll
            for (int kk = 0; kk < 16; kk++) acc = ffma2(xreg[kk], c2p[kk], acc);
            float lo, hi; unpack2(acc, lo, hi);
            sT[d1 * 161 + v2] = lo + hi;
        }
    }
    __syncthreads();

    // ---- stage 2: 800 tiles of (8 v1 x 5 v2); lane = v2 group (stride-5, cf) ----
    float* orow = out + (size_t)row * (NV1 * NV2);
    for (int it = 0; it < 4; it++) {
        int tile = it * 256 + tid;
        if (tile >= 800) break;
        int v2g = tile & 31, v1g = tile >> 5;
        int v2b = v2g * 5;
        const ull* c1p = ((const ull*)sC1p) + v1g * 4 * 32;
        ull acc[4][5];
        #pragma unroll
        for (int i = 0; i < 4; i++)
            #pragma unroll
            for (int j = 0; j < 5; j++) acc[i][j] = 0ull;
        #pragma unroll 8
        for (int k = 0; k < 32; k++) {
            ull cp[4];
            #pragma unroll
            for (int i = 0; i < 4; i++) cp[i] = c1p[i * 32 + k]; // broadcast
            ull td[5];
            #pragma unroll
            for (int j = 0; j < 5; j++) {
                float t = sT[k * 161 + v2b + j];                 // conflict-free
                td[j] = pack2(t, t);
            }
            #pragma unroll
            for (int i = 0; i < 4; i++)
                #pragma unroll
                for (int j = 0; j < 5; j++) acc[i][j] = ffma2(cp[i], td[j], acc[i][j]);
        }
        #pragma unroll
        for (int i = 0; i < 4; i++) {
            int v1 = v1g * 8 + 2 * i;
            float* p0 = orow + v1 * NV2 + v2b;
            float* p1 = p0 + NV2;
            #pragma unroll
            for (int j = 0; j < 5; j++) {
                float lo, hi; unpack2(acc[i][j], lo, hi);
                p0[j] = lo; p1[j] = hi;
            }
        }
    }
}

// ============================================================
// launcher
// ============================================================
extern "C" void kernel_launch(void* const* d_in, const int* in_sizes, int n_in,
                              void* d_out, int out_size) {
    const int*   ids   = (const int*)d_in[0];
    const float* core1 = (const float*)d_in[1];
    const float* core2 = (const float*)d_in[2];
    const float* lam   = (const float*)d_in[3];
    const float* uu    = (const float*)d_in[4];
    const float* vv    = (const float*)d_in[5];
    const float* w1    = (const float*)d_in[6];
    const float* w2    = (const float*)d_in[7];
    const float* n1w   = (const float*)d_in[8];
    const float* n2w   = (const float*)d_in[9];
    const float* fnw   = (const float*)d_in[10];
    float* out = (float*)d_out;

    cudaFuncSetAttribute(k_proj, cudaFuncAttributeMaxDynamicSharedMemorySize,
                         PROJ_SMEM_FLOATS * 4);

    // embed + layer-0 rms + layer-0 partial scan
    k_embed_fused<<<BB * NCH, 256>>>(ids, core1, core2, lam, vv, n1w);

    for (int l = 0; l < NLAY; l++) {
        int ln = (l + 1 < NLAY) ? (l + 1) : l;   // dummy (guarded) for last layer
        int last = (l == NLAY - 1) ? 1 : 0;
        k_combine<<<8, 256>>>(lam + l * DD);
        k_fused<<<BB * NCH, 256>>>(lam + l * DD, vv + l * DD, uu + l * DD,
                                   n1w + l * DD, n2w + l * DD,
                                   w1 + l * DD * 2, w2 + l * 2 * DD,
                                   lam + ln * DD, vv + ln * DD, n1w + ln * DD,
                                   last);
    }

    k_proj<<<NROWS, 256, PROJ_SMEM_FLOATS * 4>>>(core1, core2, fnw, out);
}

// round 8
// speedup vs baseline: 2.4595x; 1.2249x over previous
#include <cuda_runtime.h>
#include <cuda_bf16.h>

// ---- model constants ----
#define BB 2
#define SS 2048
#define DD 1024
#define NLAY 8
#define NV1 200
#define NV2 160
#define NCH 256       // scan chunks over S
#define TC 8          // timesteps per chunk (NCH*TC == SS)
#define NROWS (BB*SS) // 4096
#define EPSF 1e-6f

typedef unsigned long long ull;

// ---- device scratch (no allocations allowed) ----
__device__ float g_X[NROWS * DD];        // activations [B,S,D]  (16.8 MB, L2-resident)
__device__ float g_R[NROWS];             // per-row rmsnorm factors (current layer)
__device__ float g_HLOC[BB * NCH * DD];  // per-chunk local scan terminal state
__device__ float g_HIN[BB * NCH * DD];   // per-chunk incoming state

// ---- f32x2 packed-math helpers (2x fp32 FMA rate on sm_103a) ----
__device__ __forceinline__ ull pack2(float lo, float hi) {
    ull r; asm("mov.b64 %0, {%1, %2};" : "=l"(r) : "f"(lo), "f"(hi)); return r;
}
__device__ __forceinline__ void unpack2(ull v, float& lo, float& hi) {
    asm("mov.b64 {%0, %1}, %2;" : "=f"(lo), "=f"(hi) : "l"(v));
}
__device__ __forceinline__ ull ffma2(ull a, ull b, ull c) {
    ull d; asm("fma.rn.f32x2 %0, %1, %2, %3;" : "=l"(d) : "l"(a), "l"(b), "l"(c)); return d;
}

__device__ __forceinline__ float sigmoidf_acc(float x) { return 1.f / (1.f + expf(-x)); }

// jax.nn.gelu default = tanh approximation
__device__ __forceinline__ float geluf(float x) {
    float x3 = x * x * x;
    return 0.5f * x * (1.f + tanhf(0.7978845608028654f * (x + 0.044715f * x3)));
}

// 5-wide block reduce with broadcast; sbuf >= 48 floats (256 threads)
__device__ __forceinline__ void blockReduce5(float* p, float* sbuf) {
    int lane = threadIdx.x & 31, w = threadIdx.x >> 5;
    #pragma unroll
    for (int o = 16; o > 0; o >>= 1) {
        #pragma unroll
        for (int j = 0; j < 5; j++) p[j] += __shfl_down_sync(0xffffffffu, p[j], o);
    }
    if (lane == 0) {
        #pragma unroll
        for (int j = 0; j < 5; j++) sbuf[w * 5 + j] = p[j];
    }
    __syncthreads();
    if (w == 0) {
        float q[5];
        #pragma unroll
        for (int j = 0; j < 5; j++) q[j] = (lane < 8) ? sbuf[lane * 5 + j] : 0.f;
        #pragma unroll
        for (int o = 4; o > 0; o >>= 1) {
            #pragma unroll
            for (int j = 0; j < 5; j++) q[j] += __shfl_down_sync(0xffffffffu, q[j], o);
        }
        if (lane == 0) {
            #pragma unroll
            for (int j = 0; j < 5; j++) sbuf[40 + j] = q[j];
        }
    }
    __syncthreads();
    #pragma unroll
    for (int j = 0; j < 5; j++) p[j] = sbuf[40 + j];
}

// ============================================================
// 1) fused embed: TT embedding + rmsnorm factor + layer-0 partial scan
//    grid: B*NCH blocks of 256 threads; block = chunk of TC=8 rows
//    Batched reduces: 2 syncthreads total.
// ============================================================
__global__ void __launch_bounds__(256) k_embed_fused(
        const int* __restrict__ ids,
        const float* __restrict__ c1,
        const float* __restrict__ c2,
        const float* __restrict__ lam0,
        const float* __restrict__ vv0,
        const float* __restrict__ n1w0) {
    __shared__ float s1[TC][32], s2[TC][32];
    __shared__ float sW[TC * 8];   // per-row per-warp partial sums
    __shared__ float sR[TC];
    int blk = blockIdx.x; int b = blk >> 8; int ch = blk & (NCH - 1);
    int tid = threadIdx.x, lane = tid & 31, w = tid >> 5;
    int row0 = b * SS + ch * TC;

    float a[4], vi[4], N1[4];
    #pragma unroll
    for (int q = 0; q < 4; q++) {
        int c = tid + q * 256;
        a[q] = sigmoidf_acc(lam0[c]); vi[q] = vv0[c]; N1[q] = n1w0[c];
    }

    // stage TT cores for all 8 rows
    for (int i = tid; i < TC * 64; i += 256) {
        int t = i >> 6, j = i & 63;
        int id = ids[row0 + t];
        if (j < 32) s1[t][j] = c1[(id / NV2) * 32 + j];
        else        s2[t][j - 32] = c2[(id % NV2) * 32 + (j - 32)];
    }
    __syncthreads();

    float x[TC][4];
    #pragma unroll
    for (int t = 0; t < TC; t++) {
        float s = 0.f;
        #pragma unroll
        for (int q = 0; q < 4; q++) {
            int d = tid + q * 256;
            x[t][q] = s1[t][d >> 5] * s2[t][d & 31];
            s += x[t][q] * x[t][q];
        }
        #pragma unroll
        for (int o = 16; o > 0; o >>= 1) s += __shfl_down_sync(0xffffffffu, s, o);
        if (lane == 0) sW[t * 8 + w] = s;
        float* xr = g_X + (size_t)(row0 + t) * DD;
        #pragma unroll
        for (int q = 0; q < 4; q++) xr[tid + q * 256] = x[t][q];
    }
    __syncthreads();

    // warp w finalizes row w's rms factor
    {
        float s = (lane < 8) ? sW[w * 8 + lane] : 0.f;
        #pragma unroll
        for (int o = 4; o > 0; o >>= 1) s += __shfl_down_sync(0xffffffffu, s, o);
        float tot = __shfl_sync(0xffffffffu, s, 0);
        float r = rsqrtf(tot * (1.f / (float)DD) + EPSF);
        if (lane == 0) { sR[w] = r; g_R[row0 + w] = r; }
    }
    __syncthreads();

    // layer-0 partial scan (h0 = 0)
    float h[4] = {0.f, 0.f, 0.f, 0.f};
    #pragma unroll
    for (int t = 0; t < TC; t++) {
        float r = sR[t];
        #pragma unroll
        for (int q = 0; q < 4; q++) {
            float z = x[t][q] * r * N1[q];
            h[q] = a[q] * h[q] + vi[q] * z;
        }
    }
    size_t hidx = (size_t)(b * NCH + ch) * DD;
    #pragma unroll
    for (int q = 0; q < 4; q++) g_HLOC[hidx + tid + q * 256] = h[q];
}

// ============================================================
// 2) scan combine: warp-per-channel affine parallel scan over 256 chunks
//    grid: 256 blocks x 256 threads = 2048 warps (one per (b,channel))
// ============================================================
__global__ void __launch_bounds__(256) k_combine(const float* __restrict__ lam) {
    int wg = blockIdx.x * 8 + (threadIdx.x >> 5);   // 0..2047
    int lane = threadIdx.x & 31;
    int b = wg >> 10, c = wg & 1023;
    float av = sigmoidf_acc(lam[c]);
    float aT = av;
    #pragma unroll
    for (int i = 0; i < 3; i++) aT *= aT;           // a^8 = a^TC
    float aT8 = aT;
    #pragma unroll
    for (int i = 0; i < 3; i++) aT8 *= aT8;         // aT^8 (per-lane aggregate A)

    size_t base = (size_t)(b * NCH + lane * 8) * DD + c;
    float loc[8];
    #pragma unroll
    for (int j = 0; j < 8; j++) loc[j] = g_HLOC[base + (size_t)j * DD];

    // local scan aggregate: B = result of lane's 8 chunks from h0=0
    float Bv = 0.f;
    #pragma unroll
    for (int j = 0; j < 8; j++) Bv = aT * Bv + loc[j];
    float Ai = aT8, Bi = Bv;

    // inclusive Kogge-Stone over affine (A,B): cur ∘ prev
    #pragma unroll
    for (int off = 1; off < 32; off <<= 1) {
        float Ao = __shfl_up_sync(0xffffffffu, Ai, off);
        float Bo = __shfl_up_sync(0xffffffffu, Bi, off);
        if (lane >= off) { Bi = Ai * Bo + Bi; Ai = Ai * Ao; }
    }
    float hin = __shfl_up_sync(0xffffffffu, Bi, 1);
    if (lane == 0) hin = 0.f;

    float h = hin;
    #pragma unroll
    for (int j = 0; j < 8; j++) {
        g_HIN[base + (size_t)j * DD] = h;
        h = aT * h + loc[j];
    }
}

// ============================================================
// 3) fused layer kernel: scan-apply(l) + FFN(l) + next-layer rms (algebraic)
//    + next-layer partial scan. Batched reduces: 2 syncs in main path.
//    grid: B*NCH blocks of 256 threads
// ============================================================
__global__ void __launch_bounds__(256) k_fused(
        const float* __restrict__ lam, const float* __restrict__ vv,
        const float* __restrict__ uu,  const float* __restrict__ n1w,
        const float* __restrict__ n2w, const float* __restrict__ w1,
        const float* __restrict__ w2,
        const float* __restrict__ lam_n, const float* __restrict__ vv_n,
        const float* __restrict__ n1w_n, int last) {
    __shared__ float sbuf[48];
    __shared__ float sW[TC * 8 * 5];  // [row][warp][5]
    __shared__ float sS[TC * 4];      // [row]{g0,g1,rnext}
    int blk = blockIdx.x; int b = blk >> 8; int ch = blk & (NCH - 1);
    int tid = threadIdx.x, lane = tid & 31, w = tid >> 5;
    size_t hidx = (size_t)(b * NCH + ch) * DD;
    int row0 = b * SS + ch * TC;

    float a[4], vi[4], uo[4], N1[4], N2[4], W1a[4], W1b[4], W2a[4], W2b[4];
    float a2[4], vi2[4], N1n[4], h[4], h2[4];
    #pragma unroll
    for (int q = 0; q < 4; q++) {
        int c = tid + q * 256;
        a[q]  = sigmoidf_acc(lam[c]); vi[q] = vv[c]; uo[q] = uu[c];
        N1[q] = n1w[c]; N2[q] = n2w[c];
        W1a[q] = w1[2 * c]; W1b[q] = w1[2 * c + 1];
        W2a[q] = w2[c];     W2b[q] = w2[DD + c];
        h[q] = g_HIN[hidx + c];
        h2[q] = 0.f;
        a2[q] = sigmoidf_acc(lam_n[c]); vi2[q] = vv_n[c]; N1n[q] = n1w_n[c];
    }

    // quadratic sums of w2 rows (algebraic second rmsnorm)
    float Qaa, Qbb, Qab;
    {
        float p[5] = {0.f, 0.f, 0.f, 0.f, 0.f};
        #pragma unroll
        for (int q = 0; q < 4; q++) {
            p[0] += W2a[q] * W2a[q];
            p[1] += W2b[q] * W2b[q];
            p[2] += W2a[q] * W2b[q];
        }
        blockReduce5(p, sbuf);
        Qaa = p[0]; Qbb = p[1]; Qab = p[2];
    }

    // bulk-load all 8 rows (MLP=32) + rms factors
    float x[TC][4], rr[TC];
    #pragma unroll
    for (int t = 0; t < TC; t++) {
        const float* xr = g_X + (size_t)(row0 + t) * DD;
        #pragma unroll
        for (int q = 0; q < 4; q++) x[t][q] = xr[tid + q * 256];
    }
    #pragma unroll
    for (int t = 0; t < TC; t++) rr[t] = g_R[row0 + t];

    // Phase A: serial scan + per-row warp partial reduce (no block syncs)
    #pragma unroll
    for (int t = 0; t < TC; t++) {
        float p[5] = {0.f, 0.f, 0.f, 0.f, 0.f};
        #pragma unroll
        for (int q = 0; q < 4; q++) {
            float z = x[t][q] * rr[t] * N1[q];
            h[q] = a[q] * h[q] + vi[q] * z;
            float xp = x[t][q] + uo[q] * h[q];
            x[t][q] = xp;
            p[0] += xp * xp;
            float xw = xp * N2[q];
            p[1] += xw * W1a[q];
            p[2] += xw * W1b[q];
            p[3] += xp * W2a[q];
            p[4] += xp * W2b[q];
        }
        #pragma unroll
        for (int o = 16; o > 0; o >>= 1) {
            #pragma unroll
            for (int j = 0; j < 5; j++) p[j] += __shfl_down_sync(0xffffffffu, p[j], o);
        }
        if (lane == 0) {
            #pragma unroll
            for (int j = 0; j < 5; j++) sW[(t * 8 + w) * 5 + j] = p[j];
        }
    }
    __syncthreads();

    // Phase B: warp w finalizes row w (gelu on one warp per row)
    {
        float s = 0.f;
        if (lane < 5) {
            #pragma unroll
            for (int k = 0; k < 8; k++) s += sW[(w * 8 + k) * 5 + lane];
        }
        float p0 = __shfl_sync(0xffffffffu, s, 0);
        float p1 = __shfl_sync(0xffffffffu, s, 1);
        float p2 = __shfl_sync(0xffffffffu, s, 2);
        float p3 = __shfl_sync(0xffffffffu, s, 3);
        float p4 = __shfl_sync(0xffffffffu, s, 4);
        float r2 = rsqrtf(p0 * (1.f / (float)DD) + EPSF);
        float g0 = geluf(r2 * p1);
        float g1 = geluf(r2 * p2);
        float sf = p0 + 2.f * (g0 * p3 + g1 * p4)
                 + g0 * g0 * Qaa + g1 * g1 * Qbb + 2.f * g0 * g1 * Qab;
        float rnext = rsqrtf(sf * (1.f / (float)DD) + EPSF);
        if (lane == 0) {
            sS[w * 4 + 0] = g0; sS[w * 4 + 1] = g1; sS[w * 4 + 2] = rnext;
            g_R[row0 + w] = rnext;
        }
    }
    __syncthreads();

    // Phase C: FFN apply + store + next-layer partial scan
    #pragma unroll
    for (int t = 0; t < TC; t++) {
        float g0 = sS[t * 4 + 0], g1 = sS[t * 4 + 1], rn = sS[t * 4 + 2];
        float* xo = g_X + (size_t)(row0 + t) * DD;
        #pragma unroll
        for (int q = 0; q < 4; q++) {
            float xf = x[t][q] + g0 * W2a[q] + g1 * W2b[q];
            xo[tid + q * 256] = xf;
            if (!last) {
                float z2 = xf * rn * N1n[q];
                h2[q] = a2[q] * h2[q] + vi2[q] * z2;
            }
        }
    }
    if (!last) {
        #pragma unroll
        for (int q = 0; q < 4; q++) g_HLOC[hidx + tid + q * 256] = h2[q];
    }
}

// ============================================================
// 4) final TT-factored output projection (uses precomputed g_R)
//    stage1: T[d1,v2] = sum_d2 xf[d1,d2]*c2[v2,d2], stored pre-paired (t,t)
//    stage2: out[v1,v2] = sum_d1 c1[v1,d1]*T[d1,v2] (f32x2, v1-pairs)
//    v2 = lane + 32*j  -> fully coalesced GMEM stores
// smem (floats):
//   sXF  [32][34]        @ 0
//   sC2  [160][32]       @ 1088
//   sC1p [100][32]x2     @ 6208
//   sTd  ull[32][161]    @ 12608 (float idx) = 50432 B, size 41216 B
// total 91648 B
// ============================================================
#define PROJ_SMEM_BYTES 91648
__global__ void __launch_bounds__(256) k_proj(const float* __restrict__ c1,
                                              const float* __restrict__ c2,
                                              const float* __restrict__ fnw,
                                              float* __restrict__ out) {
    extern __shared__ float sm[];
    float* sXF  = sm;            // [32][34]
    float* sC2  = sm + 1088;     // [160][32]
    float* sC1p = sm + 6208;     // pairs: ((v1>>1)*32 + k)*2 + (v1&1)
    ull*   sTd  = (ull*)(sm + 12608);  // [32][161] pre-paired

    int row = blockIdx.x, tid = threadIdx.x;
    const float* xr = g_X + (size_t)row * DD;
    float r = g_R[row];          // final-norm factor from layer-7 kernel

    #pragma unroll
    for (int q = 0; q < 4; q++) {
        int d = tid + q * 256; int d1 = d >> 5, d2 = d & 31;
        sXF[d1 * 34 + d2] = xr[d] * r * fnw[d];
    }
    for (int i = tid; i < NV2 * 32; i += 256) sC2[i] = c2[i];
    for (int i = tid; i < NV1 * 32; i += 256) {
        int v1 = i >> 5, k = i & 31;
        sC1p[((v1 >> 1) * 32 + k) * 2 + (v1 & 1)] = c1[i];
    }
    __syncthreads();

    // ---- stage 1: thread owns d1 = tid&31, 20 v2's; write (t,t) pairs ----
    {
        int d1 = tid & 31;
        int v2b = (tid >> 5) * 20;
        const ull* xfp = (const ull*)(sXF + d1 * 34);   // 16 x (d2 pair)
        ull xreg[16];
        #pragma unroll
        for (int kk = 0; kk < 16; kk++) xreg[kk] = xfp[kk];
        for (int n = 0; n < 20; n++) {
            int v2 = v2b + n;
            const ull* c2p = (const ull*)(sC2 + v2 * 32); // broadcast across warp
            ull acc = 0ull;
            #pragma unroll
            for (int kk = 0; kk < 16; kk++) acc = ffma2(xreg[kk], c2p[kk], acc);
            float lo, hi; unpack2(acc, lo, hi);
            float t = lo + hi;
            sTd[d1 * 161 + v2] = pack2(t, t);
        }
    }
    __syncthreads();

    // ---- stage 2: 800 tiles (25 v1-groups x 32 lanes); v2 = lane + 32j ----
    float* orow = out + (size_t)row * (NV1 * NV2);
    for (int it = 0; it < 4; it++) {
        int tile = it * 256 + tid;
        if (tile >= 800) break;
        int l = tile & 31, v1g = tile >> 5;
        const ull* c1p = ((const ull*)sC1p) + v1g * 4 * 32;
        ull acc[4][5];
        #pragma unroll
        for (int i = 0; i < 4; i++)
            #pragma unroll
            for (int j = 0; j < 5; j++) acc[i][j] = 0ull;
        #pragma unroll 8
        for (int k = 0; k < 32; k++) {
            ull cp[4];
            #pragma unroll
            for (int i = 0; i < 4; i++) cp[i] = c1p[i * 32 + k]; // broadcast
            ull td[5];
            #pragma unroll
            for (int j = 0; j < 5; j++) td[j] = sTd[k * 161 + l + 32 * j];
            #pragma unroll
            for (int i = 0; i < 4; i++)
                #pragma unroll
                for (int j = 0; j < 5; j++) acc[i][j] = ffma2(cp[i], td[j], acc[i][j]);
        }
        #pragma unroll
        for (int i = 0; i < 4; i++) {
            int v1 = v1g * 8 + 2 * i;
            float* p0 = orow + v1 * NV2 + l;
            float* p1 = p0 + NV2;
            #pragma unroll
            for (int j = 0; j < 5; j++) {
                float lo, hi; unpack2(acc[i][j], lo, hi);
                p0[32 * j] = lo; p1[32 * j] = hi;   // coalesced per (i,j)
            }
        }
    }
}

// ============================================================
// launcher
// ============================================================
extern "C" void kernel_launch(void* const* d_in, const int* in_sizes, int n_in,
                              void* d_out, int out_size) {
    const int*   ids   = (const int*)d_in[0];
    const float* core1 = (const float*)d_in[1];
    const float* core2 = (const float*)d_in[2];
    const float* lam   = (const float*)d_in[3];
    const float* uu    = (const float*)d_in[4];
    const float* vv    = (const float*)d_in[5];
    const float* w1    = (const float*)d_in[6];
    const float* w2    = (const float*)d_in[7];
    const float* n1w   = (const float*)d_in[8];
    const float* n2w   = (const float*)d_in[9];
    const float* fnw   = (const float*)d_in[10];
    float* out = (float*)d_out;

    cudaFuncSetAttribute(k_proj, cudaFuncAttributeMaxDynamicSharedMemorySize,
                         PROJ_SMEM_BYTES);

    // embed + layer-0 rms + layer-0 partial scan
    k_embed_fused<<<BB * NCH, 256>>>(ids, core1, core2, lam, vv, n1w);

    for (int l = 0; l < NLAY; l++) {
        int ln = (l + 1 < NLAY) ? (l + 1) : l;   // dummy (guarded) for last layer
        int last = (l == NLAY - 1) ? 1 : 0;
        k_combine<<<BB * 1024 / 8, 256>>>(lam + l * DD);
        k_fused<<<BB * NCH, 256>>>(lam + l * DD, vv + l * DD, uu + l * DD,
                                   n1w + l * DD, n2w + l * DD,
                                   w1 + l * DD * 2, w2 + l * 2 * DD,
                                   lam + ln * DD, vv + ln * DD, n1w + ln * DD,
                                   last);
    }

    k_proj<<<NROWS, 256, PROJ_SMEM_BYTES>>>(core1, core2, fnw, out);
}

// round 10
// speedup vs baseline: 2.9443x; 1.1971x over previous
#include <cuda_runtime.h>
#include <cuda_bf16.h>

// ---- model constants ----
#define BB 2
#define SS 2048
#define DD 1024
#define NLAY 8
#define NV1 200
#define NV2 160
#define NCH 256       // scan chunks over S
#define TC 8          // timesteps per chunk (NCH*TC == SS)
#define NROWS (BB*SS) // 4096
#define EPSF 1e-6f

typedef unsigned long long ull;

// ---- device scratch (no allocations allowed) ----
__device__ float g_X[NROWS * DD];        // activations [B,S,D]  (16.8 MB, L2-resident)
__device__ float g_R[NROWS];             // per-row rmsnorm factors (current layer)
__device__ float g_HLOC[BB * NCH * DD];  // per-chunk local scan terminal state
__device__ float g_HIN[BB * NCH * DD];   // per-chunk incoming state

// ---- f32x2 packed-math helpers (2x fp32 FMA rate on sm_103a) ----
__device__ __forceinline__ ull pack2(float lo, float hi) {
    ull r; asm("mov.b64 %0, {%1, %2};" : "=l"(r) : "f"(lo), "f"(hi)); return r;
}
__device__ __forceinline__ void unpack2(ull v, float& lo, float& hi) {
    asm("mov.b64 {%0, %1}, %2;" : "=f"(lo), "=f"(hi) : "l"(v));
}
__device__ __forceinline__ ull ffma2(ull a, ull b, ull c) {
    ull d; asm("fma.rn.f32x2 %0, %1, %2, %3;" : "=l"(d) : "l"(a), "l"(b), "l"(c)); return d;
}

__device__ __forceinline__ float sigmoidf_acc(float x) { return 1.f / (1.f + expf(-x)); }

// jax.nn.gelu default = tanh approximation
__device__ __forceinline__ float geluf(float x) {
    float x3 = x * x * x;
    return 0.5f * x * (1.f + tanhf(0.7978845608028654f * (x + 0.044715f * x3)));
}

// 5-wide block reduce with broadcast; sbuf >= 48 floats (256 threads)
__device__ __forceinline__ void blockReduce5(float* p, float* sbuf) {
    int lane = threadIdx.x & 31, w = threadIdx.x >> 5;
    #pragma unroll
    for (int o = 16; o > 0; o >>= 1) {
        #pragma unroll
        for (int j = 0; j < 5; j++) p[j] += __shfl_down_sync(0xffffffffu, p[j], o);
    }
    if (lane == 0) {
        #pragma unroll
        for (int j = 0; j < 5; j++) sbuf[w * 5 + j] = p[j];
    }
    __syncthreads();
    if (w == 0) {
        float q[5];
        #pragma unroll
        for (int j = 0; j < 5; j++) q[j] = (lane < 8) ? sbuf[lane * 5 + j] : 0.f;
        #pragma unroll
        for (int o = 4; o > 0; o >>= 1) {
            #pragma unroll
            for (int j = 0; j < 5; j++) q[j] += __shfl_down_sync(0xffffffffu, q[j], o);
        }
        if (lane == 0) {
            #pragma unroll
            for (int j = 0; j < 5; j++) sbuf[40 + j] = q[j];
        }
    }
    __syncthreads();
    #pragma unroll
    for (int j = 0; j < 5; j++) p[j] = sbuf[40 + j];
}

// ============================================================
// 1) fused embed: TT embedding + rmsnorm factor + layer-0 partial scan
// ============================================================
__global__ void __launch_bounds__(256) k_embed_fused(
        const int* __restrict__ ids,
        const float* __restrict__ c1,
        const float* __restrict__ c2,
        const float* __restrict__ lam0,
        const float* __restrict__ vv0,
        const float* __restrict__ n1w0) {
    __shared__ float s1[TC][32], s2[TC][32];
    __shared__ float sW[TC * 8];   // per-row per-warp partial sums
    __shared__ float sR[TC];
    int blk = blockIdx.x; int b = blk >> 8; int ch = blk & (NCH - 1);
    int tid = threadIdx.x, lane = tid & 31, w = tid >> 5;
    int row0 = b * SS + ch * TC;

    float a[4], vi[4], N1[4];
    #pragma unroll
    for (int q = 0; q < 4; q++) {
        int c = tid + q * 256;
        a[q] = sigmoidf_acc(lam0[c]); vi[q] = vv0[c]; N1[q] = n1w0[c];
    }

    // stage TT cores for all 8 rows
    for (int i = tid; i < TC * 64; i += 256) {
        int t = i >> 6, j = i & 63;
        int id = ids[row0 + t];
        if (j < 32) s1[t][j] = c1[(id / NV2) * 32 + j];
        else        s2[t][j - 32] = c2[(id % NV2) * 32 + (j - 32)];
    }
    __syncthreads();

    float x[TC][4];
    #pragma unroll
    for (int t = 0; t < TC; t++) {
        float s = 0.f;
        #pragma unroll
        for (int q = 0; q < 4; q++) {
            int d = tid + q * 256;
            x[t][q] = s1[t][d >> 5] * s2[t][d & 31];
            s += x[t][q] * x[t][q];
        }
        #pragma unroll
        for (int o = 16; o > 0; o >>= 1) s += __shfl_down_sync(0xffffffffu, s, o);
        if (lane == 0) sW[t * 8 + w] = s;
        float* xr = g_X + (size_t)(row0 + t) * DD;
        #pragma unroll
        for (int q = 0; q < 4; q++) xr[tid + q * 256] = x[t][q];
    }
    __syncthreads();

    // warp w finalizes row w's rms factor
    {
        float s = (lane < 8) ? sW[w * 8 + lane] : 0.f;
        #pragma unroll
        for (int o = 4; o > 0; o >>= 1) s += __shfl_down_sync(0xffffffffu, s, o);
        float tot = __shfl_sync(0xffffffffu, s, 0);
        float r = rsqrtf(tot * (1.f / (float)DD) + EPSF);
        if (lane == 0) { sR[w] = r; g_R[row0 + w] = r; }
    }
    __syncthreads();

    // layer-0 partial scan (h0 = 0)
    float h[4] = {0.f, 0.f, 0.f, 0.f};
    #pragma unroll
    for (int t = 0; t < TC; t++) {
        float r = sR[t];
        #pragma unroll
        for (int q = 0; q < 4; q++) {
            float z = x[t][q] * r * N1[q];
            h[q] = a[q] * h[q] + vi[q] * z;
        }
    }
    size_t hidx = (size_t)(b * NCH + ch) * DD;
    #pragma unroll
    for (int q = 0; q < 4; q++) g_HLOC[hidx + tid + q * 256] = h[q];
}

// ============================================================
// 2) scan combine: smem-staged, fully coalesced.
//    grid: 64 blocks x 256 threads; block = (b, 32 channels).
//    Load 256x32 tile coalesced -> warp-per-channel Kogge-Stone over
//    8 blocks of 32 chunks (uniform-decay multipliers) -> coalesced store.
// ============================================================
__global__ void __launch_bounds__(256) k_combine(const float* __restrict__ lam) {
    __shared__ float sH[NCH * 33];           // [chunk][channel] pitch 33
    int g = blockIdx.x;
    int b = g >> 5;                          // 0..1
    int c0 = (g & 31) * 32;                  // channel block
    int tid = threadIdx.x, lane = tid & 31, w = tid >> 5;

    // coalesced load: warp handles chunk k = w + 8*i, lanes span channels
    #pragma unroll 8
    for (int i = 0; i < 32; i++) {
        int k = w + 8 * i;
        sH[k * 33 + lane] = g_HLOC[(size_t)(b * NCH + k) * DD + c0 + lane];
    }
    __syncthreads();

    // warp w scans channels c_local = w*4 .. w*4+3
    for (int m = 0; m < 4; m++) {
        int cl = w * 4 + m;
        int c = c0 + cl;
        float av = sigmoidf_acc(lam[c]);
        float aT = av; aT *= aT; aT *= aT; aT *= aT;   // a^8 = a^TC
        // step multipliers aT^(2^s) and per-lane power aT^lane
        float m0 = aT, m1 = m0 * m0, m2 = m1 * m1, m3 = m2 * m2, m4 = m3 * m3;
        float pw = 1.f;
        if (lane & 1)  pw *= m0;
        if (lane & 2)  pw *= m1;
        if (lane & 4)  pw *= m2;
        if (lane & 8)  pw *= m3;
        if (lane & 16) pw *= m4;
        float aT32 = m4 * m4;

        float carry = 0.f;
        #pragma unroll
        for (int j = 0; j < 8; j++) {
            int k = j * 32 + lane;
            float B = sH[k * 33 + cl];       // conflict-free (33*32k + lane)
            // inclusive Kogge-Stone with uniform decay
            float t;
            t = __shfl_up_sync(0xffffffffu, B, 1);  if (lane >= 1)  B += m0 * t;
            t = __shfl_up_sync(0xffffffffu, B, 2);  if (lane >= 2)  B += m1 * t;
            t = __shfl_up_sync(0xffffffffu, B, 4);  if (lane >= 4)  B += m2 * t;
            t = __shfl_up_sync(0xffffffffu, B, 8);  if (lane >= 8)  B += m3 * t;
            t = __shfl_up_sync(0xffffffffu, B, 16); if (lane >= 16) B += m4 * t;
            // exclusive + carry -> h at start of chunk k
            float ex = __shfl_up_sync(0xffffffffu, B, 1);
            if (lane == 0) ex = 0.f;
            float hin = pw * carry + ex;
            float last = __shfl_sync(0xffffffffu, B, 31);
            sH[k * 33 + cl] = hin;           // overwrite with h_in
            carry = aT32 * carry + last;
        }
    }
    __syncthreads();

    // coalesced store
    #pragma unroll 8
    for (int i = 0; i < 32; i++) {
        int k = w + 8 * i;
        g_HIN[(size_t)(b * NCH + k) * DD + c0 + lane] = sH[k * 33 + lane];
    }
}

// ============================================================
// 3) fused layer kernel: scan-apply(l) + FFN(l) + next-layer rms (algebraic)
//    + next-layer partial scan.
// ============================================================
__global__ void __launch_bounds__(256) k_fused(
        const float* __restrict__ lam, const float* __restrict__ vv,
        const float* __restrict__ uu,  const float* __restrict__ n1w,
        const float* __restrict__ n2w, const float* __restrict__ w1,
        const float* __restrict__ w2,
        const float* __restrict__ lam_n, const float* __restrict__ vv_n,
        const float* __restrict__ n1w_n, int last) {
    __shared__ float sbuf[48];
    __shared__ float sW[TC * 8 * 5];  // [row][warp][5]
    __shared__ float sS[TC * 4];      // [row]{g0,g1,rnext}
    int blk = blockIdx.x; int b = blk >> 8; int ch = blk & (NCH - 1);
    int tid = threadIdx.x, lane = tid & 31, w = tid >> 5;
    size_t hidx = (size_t)(b * NCH + ch) * DD;
    int row0 = b * SS + ch * TC;

    float a[4], vi[4], uo[4], N1[4], N2[4], W1a[4], W1b[4], W2a[4], W2b[4];
    float a2[4], vi2[4], N1n[4], h[4], h2[4];
    #pragma unroll
    for (int q = 0; q < 4; q++) {
        int c = tid + q * 256;
        a[q]  = sigmoidf_acc(lam[c]); vi[q] = vv[c]; uo[q] = uu[c];
        N1[q] = n1w[c]; N2[q] = n2w[c];
        W1a[q] = w1[2 * c]; W1b[q] = w1[2 * c + 1];
        W2a[q] = w2[c];     W2b[q] = w2[DD + c];
        h[q] = g_HIN[hidx + c];
        h2[q] = 0.f;
        a2[q] = sigmoidf_acc(lam_n[c]); vi2[q] = vv_n[c]; N1n[q] = n1w_n[c];
    }

    // quadratic sums of w2 rows (algebraic second rmsnorm)
    float Qaa, Qbb, Qab;
    {
        float p[5] = {0.f, 0.f, 0.f, 0.f, 0.f};
        #pragma unroll
        for (int q = 0; q < 4; q++) {
            p[0] += W2a[q] * W2a[q];
            p[1] += W2b[q] * W2b[q];
            p[2] += W2a[q] * W2b[q];
        }
        blockReduce5(p, sbuf);
        Qaa = p[0]; Qbb = p[1]; Qab = p[2];
    }

    // bulk-load all 8 rows (MLP=32) + rms factors
    float x[TC][4], rr[TC];
    #pragma unroll
    for (int t = 0; t < TC; t++) {
        const float* xr = g_X + (size_t)(row0 + t) * DD;
        #pragma unroll
        for (int q = 0; q < 4; q++) x[t][q] = xr[tid + q * 256];
    }
    #pragma unroll
    for (int t = 0; t < TC; t++) rr[t] = g_R[row0 + t];

    // Phase A: serial scan + per-row warp partial reduce (no block syncs)
    #pragma unroll
    for (int t = 0; t < TC; t++) {
        float p[5] = {0.f, 0.f, 0.f, 0.f, 0.f};
        #pragma unroll
        for (int q = 0; q < 4; q++) {
            float z = x[t][q] * rr[t] * N1[q];
            h[q] = a[q] * h[q] + vi[q] * z;
            float xp = x[t][q] + uo[q] * h[q];
            x[t][q] = xp;
            p[0] += xp * xp;
            float xw = xp * N2[q];
            p[1] += xw * W1a[q];
            p[2] += xw * W1b[q];
            p[3] += xp * W2a[q];
            p[4] += xp * W2b[q];
        }
        #pragma unroll
        for (int o = 16; o > 0; o >>= 1) {
            #pragma unroll
            for (int j = 0; j < 5; j++) p[j] += __shfl_down_sync(0xffffffffu, p[j], o);
        }
        if (lane == 0) {
            #pragma unroll
            for (int j = 0; j < 5; j++) sW[(t * 8 + w) * 5 + j] = p[j];
        }
    }
    __syncthreads();

    // Phase B: warp w finalizes row w (gelu on one warp per row)
    {
        float s = 0.f;
        if (lane < 5) {
            #pragma unroll
            for (int k = 0; k < 8; k++) s += sW[(w * 8 + k) * 5 + lane];
        }
        float p0 = __shfl_sync(0xffffffffu, s, 0);
        float p1 = __shfl_sync(0xffffffffu, s, 1);
        float p2 = __shfl_sync(0xffffffffu, s, 2);
        float p3 = __shfl_sync(0xffffffffu, s, 3);
        float p4 = __shfl_sync(0xffffffffu, s, 4);
        float r2 = rsqrtf(p0 * (1.f / (float)DD) + EPSF);
        float g0 = geluf(r2 * p1);
        float g1 = geluf(r2 * p2);
        float sf = p0 + 2.f * (g0 * p3 + g1 * p4)
                 + g0 * g0 * Qaa + g1 * g1 * Qbb + 2.f * g0 * g1 * Qab;
        float rnext = rsqrtf(sf * (1.f / (float)DD) + EPSF);
        if (lane == 0) {
            sS[w * 4 + 0] = g0; sS[w * 4 + 1] = g1; sS[w * 4 + 2] = rnext;
            g_R[row0 + w] = rnext;
        }
    }
    __syncthreads();

    // Phase C: FFN apply + store + next-layer partial scan
    #pragma unroll
    for (int t = 0; t < TC; t++) {
        float g0 = sS[t * 4 + 0], g1 = sS[t * 4 + 1], rn = sS[t * 4 + 2];
        float* xo = g_X + (size_t)(row0 + t) * DD;
        #pragma unroll
        for (int q = 0; q < 4; q++) {
            float xf = x[t][q] + g0 * W2a[q] + g1 * W2b[q];
            xo[tid + q * 256] = xf;
            if (!last) {
                float z2 = xf * rn * N1n[q];
                h2[q] = a2[q] * h2[q] + vi2[q] * z2;
            }
        }
    }
    if (!last) {
        #pragma unroll
        for (int q = 0; q < 4; q++) g_HLOC[hidx + tid + q * 256] = h2[q];
    }
}

// ============================================================
// 4) final TT-factored output projection (uses precomputed g_R)
//    Crossbar-minimized:
//      stage1: c2 loads as LDS.128 (ulonglong2)
//      T stored as plain float; stage2 re-pairs in ALU (mov.b64)
//      c1 pre-paired AND k-grouped: [v1g][k][4 ull] -> 2x LDS.128 per k
// smem (floats):
//   sXF  [32][34]            @ 0      (1088)
//   sC2  [160][32]           @ 1088   (5120)
//   sT   [32][161]           @ 6208   (5152)
//   sC1q ull[25][32][4]      @ 11360  (3200 ull = 6400 floats), 16B aligned
// total 17760 floats = 71040 B -> 3 blocks/SM smem-wise
// ============================================================
#define PROJ_SMEM_BYTES (17760 * 4)
__global__ void __launch_bounds__(256) k_proj(const float* __restrict__ c1,
                                              const float* __restrict__ c2,
                                              const float* __restrict__ fnw,
                                              float* __restrict__ out) {
    extern __shared__ float sm[];
    float* sXF  = sm;                  // [32][34]
    float* sC2  = sm + 1088;           // [160][32]
    float* sT   = sm + 6208;           // [32][161] plain float
    ull*   sC1q = (ull*)(sm + 11360);  // [v1g][k][i] pre-paired

    int row = blockIdx.x, tid = threadIdx.x;
    const float* xr = g_X + (size_t)row * DD;
    float r = g_R[row];                // final-norm factor from layer-7 kernel

    #pragma unroll
    for (int q = 0; q < 4; q++) {
        int d = tid + q * 256; int d1 = d >> 5, d2 = d & 31;
        sXF[d1 * 34 + d2] = xr[d] * r * fnw[d];
    }
    for (int i = tid; i < NV2 * 32; i += 256) sC2[i] = c2[i];
    // c1 pairs (v1 even, v1 odd), grouped so the 4 pair-ulls of one k are adjacent
    for (int i = tid; i < 100 * 32; i += 256) {
        int p = i >> 5, k = i & 31;          // p = v1 pair index 0..99
        int v1g = p >> 2, ii = p & 3;
        float lo = c1[(2 * p) * 32 + k];
        float hi = c1[(2 * p + 1) * 32 + k];
        sC1q[(v1g * 32 + k) * 4 + ii] = pack2(lo, hi);
    }
    __syncthreads();

    // ---- stage 1: thread owns d1 = tid&31, 20 v2's; LDS.128 c2 loads ----
    {
        int d1 = tid & 31;
        int v2b = (tid >> 5) * 20;
        const ull* xfp = (const ull*)(sXF + d1 * 34);   // 16 x (d2 pair)
        ull xreg[16];
        #pragma unroll
        for (int kk = 0; kk < 16; kk++) xreg[kk] = xfp[kk];
        for (int n = 0; n < 20; n++) {
            int v2 = v2b + n;
            const ulonglong2* c2q = (const ulonglong2*)(sC2 + v2 * 32);
            ull acc = 0ull;
            #pragma unroll
            for (int kk = 0; kk < 8; kk++) {
                ulonglong2 cc = c2q[kk];                 // 16B uniform broadcast
                acc = ffma2(xreg[2 * kk],     cc.x, acc);
                acc = ffma2(xreg[2 * kk + 1], cc.y, acc);
            }
            float lo, hi; unpack2(acc, lo, hi);
            sT[d1 * 161 + v2] = lo + hi;
        }
    }
    __syncthreads();

    // ---- stage 2: 800 tiles (25 v1-groups x 32 lanes); v2 = lane + 32j ----
    float* orow = out + (size_t)row * (NV1 * NV2);
    for (int it = 0; it < 4; it++) {
        int tile = it * 256 + tid;
        if (tile >= 800) break;
        int l = tile & 31, v1g = tile >> 5;
        const ulonglong2* c1p = (const ulonglong2*)(sC1q + v1g * 32 * 4);
        ull acc[4][5];
        #pragma unroll
        for (int i = 0; i < 4; i++)
            #pragma unroll
            for (int j = 0; j < 5; j++) acc[i][j] = 0ull;
        #pragma unroll 8
        for (int k = 0; k < 32; k++) {
            ulonglong2 q0 = c1p[2 * k];          // pairs i=0,1 (uniform LDS.128)
            ulonglong2 q1 = c1p[2 * k + 1];      // pairs i=2,3
            ull cp[4] = {q0.x, q0.y, q1.x, q1.y};
            ull td[5];
            #pragma unroll
            for (int j = 0; j < 5; j++) {
                float t = sT[k * 161 + l + 32 * j];   // LDS.32, 1 wavefront
                td[j] = pack2(t, t);                   // ALU pipe
            }
            #pragma unroll
            for (int i = 0; i < 4; i++)
                #pragma unroll
                for (int j = 0; j < 5; j++) acc[i][j] = ffma2(cp[i], td[j], acc[i][j]);
        }
        #pragma unroll
        for (int i = 0; i < 4; i++) {
            int v1 = v1g * 8 + 2 * i;
            float* p0 = orow + v1 * NV2 + l;
            float* p1 = p0 + NV2;
            #pragma unroll
            for (int j = 0; j < 5; j++) {
                float lo, hi; unpack2(acc[i][j], lo, hi);
                p0[32 * j] = lo; p1[32 * j] = hi;   // coalesced per (i,j)
            }
        }
    }
}

// ============================================================
// launcher
// ============================================================
extern "C" void kernel_launch(void* const* d_in, const int* in_sizes, int n_in,
                              void* d_out, int out_size) {
    const int*   ids   = (const int*)d_in[0];
    const float* core1 = (const float*)d_in[1];
    const float* core2 = (const float*)d_in[2];
    const float* lam   = (const float*)d_in[3];
    const float* uu    = (const float*)d_in[4];
    const float* vv    = (const float*)d_in[5];
    const float* w1    = (const float*)d_in[6];
    const float* w2    = (const float*)d_in[7];
    const float* n1w   = (const float*)d_in[8];
    const float* n2w   = (const float*)d_in[9];
    const float* fnw   = (const float*)d_in[10];
    float* out = (float*)d_out;

    cudaFuncSetAttribute(k_proj, cudaFuncAttributeMaxDynamicSharedMemorySize,
                         PROJ_SMEM_BYTES);

    // embed + layer-0 rms + layer-0 partial scan
    k_embed_fused<<<BB * NCH, 256>>>(ids, core1, core2, lam, vv, n1w);

    for (int l = 0; l < NLAY; l++) {
        int ln = (l + 1 < NLAY) ? (l + 1) : l;   // dummy (guarded) for last layer
        int last = (l == NLAY - 1) ? 1 : 0;
        k_combine<<<64, 256>>>(lam + l * DD);
        k_fused<<<BB * NCH, 256>>>(lam + l * DD, vv + l * DD, uu + l * DD,
                                   n1w + l * DD, n2w + l * DD,
                                   w1 + l * DD * 2, w2 + l * 2 * DD,
                                   lam + ln * DD, vv + ln * DD, n1w + ln * DD,
                                   last);
    }

    k_proj<<<NROWS, 256, PROJ_SMEM_BYTES>>>(core1, core2, fnw, out);
}

// round 13
// speedup vs baseline: 2.9890x; 1.0152x over previous
#include <cuda_runtime.h>
#include <cuda_bf16.h>

// ---- model constants ----
#define BB 2
#define SS 2048
#define DD 1024
#define NLAY 8
#define NV1 200
#define NV2 160
#define NCH 256       // scan chunks over S
#define TC 8          // timesteps per chunk (NCH*TC == SS)
#define NROWS (BB*SS) // 4096
#define EPSF 1e-6f

typedef unsigned long long ull;

// ---- device scratch (no allocations allowed) ----
__device__ float g_X[NROWS * DD];        // activations [B,S,D]  (16.8 MB, L2-resident)
__device__ float g_R[NROWS];             // per-row rmsnorm factors (current layer)
__device__ float g_HLOC[BB * NCH * DD];  // per-chunk local scan terminal state
__device__ float g_HIN[BB * NCH * DD];   // per-chunk incoming state

// ---- f32x2 packed-math helpers (2x fp32 FMA rate on sm_103a) ----
__device__ __forceinline__ ull pack2(float lo, float hi) {
    ull r; asm("mov.b64 %0, {%1, %2};" : "=l"(r) : "f"(lo), "f"(hi)); return r;
}
__device__ __forceinline__ void unpack2(ull v, float& lo, float& hi) {
    asm("mov.b64 {%0, %1}, %2;" : "=f"(lo), "=f"(hi) : "l"(v));
}
__device__ __forceinline__ ull ffma2(ull a, ull b, ull c) {
    ull d; asm("fma.rn.f32x2 %0, %1, %2, %3;" : "=l"(d) : "l"(a), "l"(b), "l"(c)); return d;
}

__device__ __forceinline__ float sigmoidf_acc(float x) { return 1.f / (1.f + expf(-x)); }

// jax.nn.gelu default = tanh approximation
__device__ __forceinline__ float geluf(float x) {
    float x3 = x * x * x;
    return 0.5f * x * (1.f + tanhf(0.7978845608028654f * (x + 0.044715f * x3)));
}

// 5-wide block reduce with broadcast; sbuf >= 48 floats (256 threads)
__device__ __forceinline__ void blockReduce5(float* p, float* sbuf) {
    int lane = threadIdx.x & 31, w = threadIdx.x >> 5;
    #pragma unroll
    for (int o = 16; o > 0; o >>= 1) {
        #pragma unroll
        for (int j = 0; j < 5; j++) p[j] += __shfl_down_sync(0xffffffffu, p[j], o);
    }
    if (lane == 0) {
        #pragma unroll
        for (int j = 0; j < 5; j++) sbuf[w * 5 + j] = p[j];
    }
    __syncthreads();
    if (w == 0) {
        float q[5];
        #pragma unroll
        for (int j = 0; j < 5; j++) q[j] = (lane < 8) ? sbuf[lane * 5 + j] : 0.f;
        #pragma unroll
        for (int o = 4; o > 0; o >>= 1) {
            #pragma unroll
            for (int j = 0; j < 5; j++) q[j] += __shfl_down_sync(0xffffffffu, q[j], o);
        }
        if (lane == 0) {
            #pragma unroll
            for (int j = 0; j < 5; j++) sbuf[40 + j] = q[j];
        }
    }
    __syncthreads();
    #pragma unroll
    for (int j = 0; j < 5; j++) p[j] = sbuf[40 + j];
}

// ============================================================
// 1) fused embed: TT embedding + rmsnorm factor + layer-0 partial scan
// ============================================================
__global__ void __launch_bounds__(256) k_embed_fused(
        const int* __restrict__ ids,
        const float* __restrict__ c1,
        const float* __restrict__ c2,
        const float* __restrict__ lam0,
        const float* __restrict__ vv0,
        const float* __restrict__ n1w0) {
    __shared__ float s1[TC][32], s2[TC][32];
    __shared__ float sW[TC * 8];   // per-row per-warp partial sums
    __shared__ float sR[TC];
    int blk = blockIdx.x; int b = blk >> 8; int ch = blk & (NCH - 1);
    int tid = threadIdx.x, lane = tid & 31, w = tid >> 5;
    int row0 = b * SS + ch * TC;

    float a[4], vi[4], N1[4];
    #pragma unroll
    for (int q = 0; q < 4; q++) {
        int c = tid + q * 256;
        a[q] = sigmoidf_acc(lam0[c]); vi[q] = vv0[c]; N1[q] = n1w0[c];
    }

    // stage TT cores for all 8 rows
    for (int i = tid; i < TC * 64; i += 256) {
        int t = i >> 6, j = i & 63;
        int id = ids[row0 + t];
        if (j < 32) s1[t][j] = c1[(id / NV2) * 32 + j];
        else        s2[t][j - 32] = c2[(id % NV2) * 32 + (j - 32)];
    }
    __syncthreads();

    float x[TC][4];
    #pragma unroll
    for (int t = 0; t < TC; t++) {
        float s = 0.f;
        #pragma unroll
        for (int q = 0; q < 4; q++) {
            int d = tid + q * 256;
            x[t][q] = s1[t][d >> 5] * s2[t][d & 31];
            s += x[t][q] * x[t][q];
        }
        #pragma unroll
        for (int o = 16; o > 0; o >>= 1) s += __shfl_down_sync(0xffffffffu, s, o);
        if (lane == 0) sW[t * 8 + w] = s;
        float* xr = g_X + (size_t)(row0 + t) * DD;
        #pragma unroll
        for (int q = 0; q < 4; q++) xr[tid + q * 256] = x[t][q];
    }
    __syncthreads();

    // warp w finalizes row w's rms factor
    {
        float s = (lane < 8) ? sW[w * 8 + lane] : 0.f;
        #pragma unroll
        for (int o = 4; o > 0; o >>= 1) s += __shfl_down_sync(0xffffffffu, s, o);
        float tot = __shfl_sync(0xffffffffu, s, 0);
        float r = rsqrtf(tot * (1.f / (float)DD) + EPSF);
        if (lane == 0) { sR[w] = r; g_R[row0 + w] = r; }
    }
    __syncthreads();

    // layer-0 partial scan (h0 = 0)
    float h[4] = {0.f, 0.f, 0.f, 0.f};
    #pragma unroll
    for (int t = 0; t < TC; t++) {
        float r = sR[t];
        #pragma unroll
        for (int q = 0; q < 4; q++) {
            float z = x[t][q] * r * N1[q];
            h[q] = a[q] * h[q] + vi[q] * z;
        }
    }
    size_t hidx = (size_t)(b * NCH + ch) * DD;
    #pragma unroll
    for (int q = 0; q < 4; q++) g_HLOC[hidx + tid + q * 256] = h[q];
}

// ============================================================
// 2) scan combine: 256 blocks, 8 channels/block, 1 channel PER WARP.
//    No serial channel loop; full-chip single wave.
//    smem tile [256][9]: scan reads stride-9 (gcd(9,32)=1, conflict-free).
// ============================================================
__global__ void __launch_bounds__(256) k_combine(const float* __restrict__ lam) {
    __shared__ float sH[NCH * 9];            // [chunk][8 channels] pitch 9
    int g = blockIdx.x;                      // 0..255
    int b = g >> 7;                          // 0..1
    int c0 = (g & 127) * 8;                  // 8-channel slice
    int tid = threadIdx.x, lane = tid & 31, w = tid >> 5;

    // load 256 chunks x 8 channels
    for (int i = tid; i < NCH * 8; i += 256) {
        int k = i >> 3, cl = i & 7;
        sH[k * 9 + cl] = g_HLOC[(size_t)(b * NCH + k) * DD + c0 + cl];
    }
    __syncthreads();

    // warp w scans channel c0 + w over 8 groups of 32 chunks
    {
        int cl = w;
        int c = c0 + cl;
        float av = sigmoidf_acc(lam[c]);
        float aT = av; aT *= aT; aT *= aT; aT *= aT;   // a^8 = a^TC
        float m0 = aT, m1 = m0 * m0, m2 = m1 * m1, m3 = m2 * m2, m4 = m3 * m3;
        float pw = 1.f;
        if (lane & 1)  pw *= m0;
        if (lane & 2)  pw *= m1;
        if (lane & 4)  pw *= m2;
        if (lane & 8)  pw *= m3;
        if (lane & 16) pw *= m4;
        float aT32 = m4 * m4;

        float carry = 0.f;
        #pragma unroll
        for (int j = 0; j < 8; j++) {
            int k = j * 32 + lane;
            float B = sH[k * 9 + cl];
            // inclusive Kogge-Stone with uniform decay
            float t;
            t = __shfl_up_sync(0xffffffffu, B, 1);  if (lane >= 1)  B += m0 * t;
            t = __shfl_up_sync(0xffffffffu, B, 2);  if (lane >= 2)  B += m1 * t;
            t = __shfl_up_sync(0xffffffffu, B, 4);  if (lane >= 4)  B += m2 * t;
            t = __shfl_up_sync(0xffffffffu, B, 8);  if (lane >= 8)  B += m3 * t;
            t = __shfl_up_sync(0xffffffffu, B, 16); if (lane >= 16) B += m4 * t;
            // exclusive + carry -> h at start of chunk k
            float ex = __shfl_up_sync(0xffffffffu, B, 1);
            if (lane == 0) ex = 0.f;
            float hin = pw * carry + ex;
            float last = __shfl_sync(0xffffffffu, B, 31);
            sH[k * 9 + cl] = hin;
            carry = aT32 * carry + last;
        }
    }
    __syncthreads();

    // store h_in
    for (int i = tid; i < NCH * 8; i += 256) {
        int k = i >> 3, cl = i & 7;
        g_HIN[(size_t)(b * NCH + k) * DD + c0 + cl] = sH[k * 9 + cl];
    }
}

// ============================================================
// 3) fused layer kernel: scan-apply(l) + FFN(l) + next-layer rms (algebraic)
//    + next-layer partial scan.
// ============================================================
__global__ void __launch_bounds__(256) k_fused(
        const float* __restrict__ lam, const float* __restrict__ vv,
        const float* __restrict__ uu,  const float* __restrict__ n1w,
        const float* __restrict__ n2w, const float* __restrict__ w1,
        const float* __restrict__ w2,
        const float* __restrict__ lam_n, const float* __restrict__ vv_n,
        const float* __restrict__ n1w_n, int last) {
    __shared__ float sbuf[48];
    __shared__ float sW[TC * 8 * 5];  // [row][warp][5]
    __shared__ float sS[TC * 4];      // [row]{g0,g1,rnext}
    int blk = blockIdx.x; int b = blk >> 8; int ch = blk & (NCH - 1);
    int tid = threadIdx.x, lane = tid & 31, w = tid >> 5;
    size_t hidx = (size_t)(b * NCH + ch) * DD;
    int row0 = b * SS + ch * TC;

    float a[4], vi[4], uo[4], N1[4], N2[4], W1a[4], W1b[4], W2a[4], W2b[4];
    float a2[4], vi2[4], N1n[4], h[4], h2[4];
    #pragma unroll
    for (int q = 0; q < 4; q++) {
        int c = tid + q * 256;
        a[q]  = sigmoidf_acc(lam[c]); vi[q] = vv[c]; uo[q] = uu[c];
        N1[q] = n1w[c]; N2[q] = n2w[c];
        W1a[q] = w1[2 * c]; W1b[q] = w1[2 * c + 1];
        W2a[q] = w2[c];     W2b[q] = w2[DD + c];
        h[q] = g_HIN[hidx + c];
        h2[q] = 0.f;
        a2[q] = sigmoidf_acc(lam_n[c]); vi2[q] = vv_n[c]; N1n[q] = n1w_n[c];
    }

    // quadratic sums of w2 rows (algebraic second rmsnorm)
    float Qaa, Qbb, Qab;
    {
        float p[5] = {0.f, 0.f, 0.f, 0.f, 0.f};
        #pragma unroll
        for (int q = 0; q < 4; q++) {
            p[0] += W2a[q] * W2a[q];
            p[1] += W2b[q] * W2b[q];
            p[2] += W2a[q] * W2b[q];
        }
        blockReduce5(p, sbuf);
        Qaa = p[0]; Qbb = p[1]; Qab = p[2];
    }

    // bulk-load all 8 rows (MLP=32) + rms factors
    float x[TC][4], rr[TC];
    #pragma unroll
    for (int t = 0; t < TC; t++) {
        const float* xr = g_X + (size_t)(row0 + t) * DD;
        #pragma unroll
        for (int q = 0; q < 4; q++) x[t][q] = xr[tid + q * 256];
    }
    #pragma unroll
    for (int t = 0; t < TC; t++) rr[t] = g_R[row0 + t];

    // Phase A: serial scan + per-row warp partial reduce (no block syncs)
    #pragma unroll
    for (int t = 0; t < TC; t++) {
        float p[5] = {0.f, 0.f, 0.f, 0.f, 0.f};
        #pragma unroll
        for (int q = 0; q < 4; q++) {
            float z = x[t][q] * rr[t] * N1[q];
            h[q] = a[q] * h[q] + vi[q] * z;
            float xp = x[t][q] + uo[q] * h[q];
            x[t][q] = xp;
            p[0] += xp * xp;
            float xw = xp * N2[q];
            p[1] += xw * W1a[q];
            p[2] += xw * W1b[q];
            p[3] += xp * W2a[q];
            p[4] += xp * W2b[q];
        }
        #pragma unroll
        for (int o = 16; o > 0; o >>= 1) {
            #pragma unroll
            for (int j = 0; j < 5; j++) p[j] += __shfl_down_sync(0xffffffffu, p[j], o);
        }
        if (lane == 0) {
            #pragma unroll
            for (int j = 0; j < 5; j++) sW[(t * 8 + w) * 5 + j] = p[j];
        }
    }
    __syncthreads();

    // Phase B: warp w finalizes row w (gelu on one warp per row)
    {
        float s = 0.f;
        if (lane < 5) {
            #pragma unroll
            for (int k = 0; k < 8; k++) s += sW[(w * 8 + k) * 5 + lane];
        }
        float p0 = __shfl_sync(0xffffffffu, s, 0);
        float p1 = __shfl_sync(0xffffffffu, s, 1);
        float p2 = __shfl_sync(0xffffffffu, s, 2);
        float p3 = __shfl_sync(0xffffffffu, s, 3);
        float p4 = __shfl_sync(0xffffffffu, s, 4);
        float r2 = rsqrtf(p0 * (1.f / (float)DD) + EPSF);
        float g0 = geluf(r2 * p1);
        float g1 = geluf(r2 * p2);
        float sf = p0 + 2.f * (g0 * p3 + g1 * p4)
                 + g0 * g0 * Qaa + g1 * g1 * Qbb + 2.f * g0 * g1 * Qab;
        float rnext = rsqrtf(sf * (1.f / (float)DD) + EPSF);
        if (lane == 0) {
            sS[w * 4 + 0] = g0; sS[w * 4 + 1] = g1; sS[w * 4 + 2] = rnext;
            g_R[row0 + w] = rnext;
        }
    }
    __syncthreads();

    // Phase C: FFN apply + store + next-layer partial scan
    #pragma unroll
    for (int t = 0; t < TC; t++) {
        float g0 = sS[t * 4 + 0], g1 = sS[t * 4 + 1], rn = sS[t * 4 + 2];
        float* xo = g_X + (size_t)(row0 + t) * DD;
        #pragma unroll
        for (int q = 0; q < 4; q++) {
            float xf = x[t][q] + g0 * W2a[q] + g1 * W2b[q];
            xo[tid + q * 256] = xf;
            if (!last) {
                float z2 = xf * rn * N1n[q];
                h2[q] = a2[q] * h2[q] + vi2[q] * z2;
            }
        }
    }
    if (!last) {
        #pragma unroll
        for (int q = 0; q < 4; q++) g_HLOC[hidx + tid + q * 256] = h2[q];
    }
}

// ============================================================
// 4) final TT-factored output projection (uses precomputed g_R)
//    Crossbar-minimized (round-10 proven version).
// smem (floats):
//   sXF  [32][34]            @ 0      (1088)
//   sC2  [160][32]           @ 1088   (5120)
//   sT   [32][161]           @ 6208   (5152)
//   sC1q ull[25][32][4]      @ 11360  (6400 floats)
// total 17760 floats = 71040 B -> 3 blocks/SM smem-wise
// ============================================================
#define PROJ_SMEM_BYTES (17760 * 4)
__global__ void __launch_bounds__(256) k_proj(const float* __restrict__ c1,
                                              const float* __restrict__ c2,
                                              const float* __restrict__ fnw,
                                              float* __restrict__ out) {
    extern __shared__ float sm[];
    float* sXF  = sm;                  // [32][34]
    float* sC2  = sm + 1088;           // [160][32]
    float* sT   = sm + 6208;           // [32][161] plain float
    ull*   sC1q = (ull*)(sm + 11360);  // [v1g][k][i] pre-paired

    int row = blockIdx.x, tid = threadIdx.x;
    const float* xr = g_X + (size_t)row * DD;
    float r = g_R[row];                // final-norm factor from layer-7 kernel

    #pragma unroll
    for (int q = 0; q < 4; q++) {
        int d = tid + q * 256; int d1 = d >> 5, d2 = d & 31;
        sXF[d1 * 34 + d2] = xr[d] * r * fnw[d];
    }
    for (int i = tid; i < NV2 * 32; i += 256) sC2[i] = c2[i];
    // c1 pairs (v1 even, v1 odd), grouped so the 4 pair-ulls of one k are adjacent
    for (int i = tid; i < 100 * 32; i += 256) {
        int p = i >> 5, k = i & 31;          // p = v1 pair index 0..99
        int v1g = p >> 2, ii = p & 3;
        float lo = c1[(2 * p) * 32 + k];
        float hi = c1[(2 * p + 1) * 32 + k];
        sC1q[(v1g * 32 + k) * 4 + ii] = pack2(lo, hi);
    }
    __syncthreads();

    // ---- stage 1: thread owns d1 = tid&31, 20 v2's; LDS.128 c2 loads ----
    {
        int d1 = tid & 31;
        int v2b = (tid >> 5) * 20;
        const ull* xfp = (const ull*)(sXF + d1 * 34);   // 16 x (d2 pair)
        ull xreg[16];
        #pragma unroll
        for (int kk = 0; kk < 16; kk++) xreg[kk] = xfp[kk];
        for (int n = 0; n < 20; n++) {
            int v2 = v2b + n;
            const ulonglong2* c2q = (const ulonglong2*)(sC2 + v2 * 32);
            ull acc = 0ull;
            #pragma unroll
            for (int kk = 0; kk < 8; kk++) {
                ulonglong2 cc = c2q[kk];                 // 16B uniform broadcast
                acc = ffma2(xreg[2 * kk],     cc.x, acc);
                acc = ffma2(xreg[2 * kk + 1], cc.y, acc);
            }
            float lo, hi; unpack2(acc, lo, hi);
            sT[d1 * 161 + v2] = lo + hi;
        }
    }
    __syncthreads();

    // ---- stage 2: 800 tiles (25 v1-groups x 32 lanes); v2 = lane + 32j ----
    float* orow = out + (size_t)row * (NV1 * NV2);
    for (int it = 0; it < 4; it++) {
        int tile = it * 256 + tid;
        if (tile >= 800) break;
        int l = tile & 31, v1g = tile >> 5;
        const ulonglong2* c1p = (const ulonglong2*)(sC1q + v1g * 32 * 4);
        ull acc[4][5];
        #pragma unroll
        for (int i = 0; i < 4; i++)
            #pragma unroll
            for (int j = 0; j < 5; j++) acc[i][j] = 0ull;
        #pragma unroll 8
        for (int k = 0; k < 32; k++) {
            ulonglong2 q0 = c1p[2 * k];          // pairs i=0,1 (uniform LDS.128)
            ulonglong2 q1 = c1p[2 * k + 1];      // pairs i=2,3
            ull cp[4] = {q0.x, q0.y, q1.x, q1.y};
            ull td[5];
            #pragma unroll
            for (int j = 0; j < 5; j++) {
                float t = sT[k * 161 + l + 32 * j];   // LDS.32, 1 wavefront
                td[j] = pack2(t, t);                   // ALU pipe
            }
            #pragma unroll
            for (int i = 0; i < 4; i++)
                #pragma unroll
                for (int j = 0; j < 5; j++) acc[i][j] = ffma2(cp[i], td[j], acc[i][j]);
        }
        #pragma unroll
        for (int i = 0; i < 4; i++) {
            int v1 = v1g * 8 + 2 * i;
            float* p0 = orow + v1 * NV2 + l;
            float* p1 = p0 + NV2;
            #pragma unroll
            for (int j = 0; j < 5; j++) {
                float lo, hi; unpack2(acc[i][j], lo, hi);
                p0[32 * j] = lo; p1[32 * j] = hi;   // coalesced per (i,j)
            }
        }
    }
}

// ============================================================
// launcher
// ============================================================
extern "C" void kernel_launch(void* const* d_in, const int* in_sizes, int n_in,
                              void* d_out, int out_size) {
    const int*   ids   = (const int*)d_in[0];
    const float* core1 = (const float*)d_in[1];
    const float* core2 = (const float*)d_in[2];
    const float* lam   = (const float*)d_in[3];
    const float* uu    = (const float*)d_in[4];
    const float* vv    = (const float*)d_in[5];
    const float* w1    = (const float*)d_in[6];
    const float* w2    = (const float*)d_in[7];
    const float* n1w   = (const float*)d_in[8];
    const float* n2w   = (const float*)d_in[9];
    const float* fnw   = (const float*)d_in[10];
    float* out = (float*)d_out;

    cudaFuncSetAttribute(k_proj, cudaFuncAttributeMaxDynamicSharedMemorySize,
                         PROJ_SMEM_BYTES);

    // embed + layer-0 rms + layer-0 partial scan
    k_embed_fused<<<BB * NCH, 256>>>(ids, core1, core2, lam, vv, n1w);

    for (int l = 0; l < NLAY; l++) {
        int ln = (l + 1 < NLAY) ? (l + 1) : l;   // dummy (guarded) for last layer
        int last = (l == NLAY - 1) ? 1 : 0;
        k_combine<<<256, 256>>>(lam + l * DD);
        k_fused<<<BB * NCH, 256>>>(lam + l * DD, vv + l * DD, uu + l * DD,
                                   n1w + l * DD, n2w + l * DD,
                                   w1 + l * DD * 2, w2 + l * 2 * DD,
                                   lam + ln * DD, vv + ln * DD, n1w + ln * DD,
                                   last);
    }

    k_proj<<<NROWS, 256, PROJ_SMEM_BYTES>>>(core1, core2, fnw, out);
}